// round 2
// baseline (speedup 1.0000x reference)
#include <cuda_runtime.h>

#define V_TOT 100000
#define KN    64
#define FN    16

typedef unsigned long long u64;

// ---- packed f32x2 helpers (Blackwell FFMA2; ptxas never emits from C++) ----
__device__ __forceinline__ u64 pack2(float a, float b) {
    u64 r;
    asm("mov.b64 %0, {%1, %2};" : "=l"(r) : "r"(__float_as_uint(a)), "r"(__float_as_uint(b)));
    return r;
}
__device__ __forceinline__ void unpack2(u64 v, float& a, float& b) {
    unsigned lo, hi;
    asm("mov.b64 {%0, %1}, %2;" : "=r"(lo), "=r"(hi) : "l"(v));
    a = __uint_as_float(lo); b = __uint_as_float(hi);
}
__device__ __forceinline__ u64 fma2(u64 a, u64 b, u64 c) {
    u64 d;
    asm("fma.rn.f32x2 %0, %1, %2, %3;" : "=l"(d) : "l"(a), "l"(b), "l"(c));
    return d;
}
__device__ __forceinline__ float elu1(float x) {
    return x > 0.f ? x : (__expf(x) - 1.f);
}

__global__ __launch_bounds__(128, 2)
void napca_kernel(const float* __restrict__ coords,
                  const float* __restrict__ distsq,
                  const float* __restrict__ feats,
                  const int*   __restrict__ nidx,
                  const float* __restrict__ W0, const float* __restrict__ b0,
                  const float* __restrict__ W1, const float* __restrict__ b1,
                  const float* __restrict__ W2, const float* __restrict__ b2,
                  const float* __restrict__ W3, const float* __restrict__ b3,
                  float* __restrict__ out)
{
    __shared__ __align__(16) float sW0[9 * 64];
    __shared__ __align__(16) float sW1[64 * 64];
    __shared__ __align__(16) float sW2[64 * 64];
    __shared__ __align__(16) float sW3[64 * 16];   // W3 [64,9] padded to [64,16]
    __shared__ __align__(16) float sb0[64], sb1[64], sb2[64];
    __shared__ __align__(16) float sb3[16];
    __shared__ __align__(16) float4 sC[8 * KN];    // (cx, cy, cz, exp(-10*d2)) per (v,k)
    __shared__ int sIdx[8 * KN];

    const int tid = threadIdx.x;
    const int v0  = blockIdx.x * 8;

    // ---- weight staging (coalesced; weights are L2-hot across 12500 blocks) ----
    for (int i = tid; i < 9 * 64;  i += 128) sW0[i] = W0[i];
    for (int i = tid; i < 64 * 64; i += 128) { sW1[i] = W1[i]; sW2[i] = W2[i]; }
    for (int i = tid; i < 64 * 16; i += 128) {
        int c = i & 15;
        sW3[i] = (c < 9) ? W3[(i >> 4) * 9 + c] : 0.f;
    }
    if (tid < 64) { sb0[tid] = b0[tid]; sb1[tid] = b1[tid]; sb2[tid] = b2[tid]; }
    if (tid < 16) sb3[tid] = (tid < 9) ? b3[tid] : 0.f;

    // ---- per-vertex neighbour staging: idx + (coords, e) loaded ONCE per block ----
    #pragma unroll
    for (int t = 0; t < 4; t++) {
        int i   = tid + t * 128;              // 0..511  (8 vertices x 64 neighbours)
        int g   = v0 * KN + i;
        int idx = nidx[g];
        sIdx[i] = idx;
        float e = __expf(-10.f * distsq[g]);
        const float* cp = coords + idx * 3;
        sC[i] = make_float4(cp[0], cp[1], cp[2], e);
    }
    __syncthreads();

    const int vl = tid >> 4;          // vertex-in-block 0..7
    const int f  = tid & 15;          // feature 0..15
    const int v  = v0 + vl;

    // ---- weighted covariance: broadcast LDS.128 coords + coalesced feat LDG ----
    float s = 0.f, mx = 0.f, my = 0.f, mz = 0.f;
    float pxx = 0.f, pxy = 0.f, pxz = 0.f, pyy = 0.f, pyz = 0.f, pzz = 0.f;
    const float4* cb = sC   + vl * KN;
    const int*    ib = sIdx + vl * KN;
    #pragma unroll 8
    for (int k = 0; k < KN; k++) {
        float4 c = cb[k];
        float  w = __ldg(&feats[ib[k] * FN + f]) * c.w;
        s += w;
        float wx = w * c.x, wy = w * c.y, wz = w * c.z;
        mx += wx; my += wy; mz += wz;
        pxx = fmaf(wx, c.x, pxx); pxy = fmaf(wx, c.y, pxy); pxz = fmaf(wx, c.z, pxz);
        pyy = fmaf(wy, c.y, pyy); pyz = fmaf(wy, c.z, pyz);
        pzz = fmaf(wz, c.z, pzz);
    }
    float inv = 1.f / (s + 1e-4f);
    float ux = mx * inv, uy = my * inv, uz = mz * inv;

    float x9[9];
    x9[0] = fmaf(-ux, ux, pxx * inv);
    x9[1] = fmaf(-ux, uy, pxy * inv);
    x9[2] = fmaf(-ux, uz, pxz * inv);
    x9[3] = x9[1];
    x9[4] = fmaf(-uy, uy, pyy * inv);
    x9[5] = fmaf(-uy, uz, pyz * inv);
    x9[6] = x9[2];
    x9[7] = x9[5];
    x9[8] = fmaf(-uz, uz, pzz * inv);

    // ---- MLP 9 -> 64 -> 64 -> 64 -> 9, ELU everywhere; f32x2 over channel pairs ----
    float a[64];

    // layer 0: 9 -> 64 (LDS.128 -> two fma2 each)
    {
        u64 acc[32];
        const ulonglong2* bb = (const ulonglong2*)sb0;
        #pragma unroll
        for (int q = 0; q < 16; q++) { ulonglong2 t = bb[q]; acc[2*q] = t.x; acc[2*q+1] = t.y; }
        #pragma unroll
        for (int i = 0; i < 9; i++) {
            u64 xi = pack2(x9[i], x9[i]);
            const ulonglong2* row = (const ulonglong2*)(sW0 + i * 64);
            #pragma unroll
            for (int q = 0; q < 16; q++) {
                ulonglong2 wv = row[q];
                acc[2*q]   = fma2(xi, wv.x, acc[2*q]);
                acc[2*q+1] = fma2(xi, wv.y, acc[2*q+1]);
            }
        }
        #pragma unroll
        for (int j = 0; j < 32; j++) {
            float lo, hi; unpack2(acc[j], lo, hi);
            a[2*j] = elu1(lo); a[2*j+1] = elu1(hi);
        }
    }

    // layers 1,2: 64 -> 64 (one shared body; i-loop unrolled x2 for I$ residency)
    #pragma unroll 1
    for (int layer = 0; layer < 2; layer++) {
        const float* W = (layer == 0) ? sW1 : sW2;
        const float* B = (layer == 0) ? sb1 : sb2;
        u64 acc[32];
        const ulonglong2* bb = (const ulonglong2*)B;
        #pragma unroll
        for (int q = 0; q < 16; q++) { ulonglong2 t = bb[q]; acc[2*q] = t.x; acc[2*q+1] = t.y; }
        #pragma unroll 2
        for (int i = 0; i < 64; i++) {
            u64 xi = pack2(a[i], a[i]);
            const ulonglong2* row = (const ulonglong2*)(W + i * 64);
            #pragma unroll
            for (int q = 0; q < 16; q++) {
                ulonglong2 wv = row[q];
                acc[2*q]   = fma2(xi, wv.x, acc[2*q]);
                acc[2*q+1] = fma2(xi, wv.y, acc[2*q+1]);
            }
        }
        #pragma unroll
        for (int j = 0; j < 32; j++) {
            float lo, hi; unpack2(acc[j], lo, hi);
            a[2*j] = elu1(lo); a[2*j+1] = elu1(hi);
        }
    }

    // layer 3: 64 -> 9 (padded 16)
    {
        u64 acc3[8];
        const ulonglong2* bb = (const ulonglong2*)sb3;
        #pragma unroll
        for (int q = 0; q < 4; q++) { ulonglong2 t = bb[q]; acc3[2*q] = t.x; acc3[2*q+1] = t.y; }
        #pragma unroll 4
        for (int i = 0; i < 64; i++) {
            u64 xi = pack2(a[i], a[i]);
            const ulonglong2* row = (const ulonglong2*)(sW3 + i * 16);
            #pragma unroll
            for (int q = 0; q < 4; q++) {
                ulonglong2 wv = row[q];
                acc3[2*q]   = fma2(xi, wv.x, acc3[2*q]);
                acc3[2*q+1] = fma2(xi, wv.y, acc3[2*q+1]);
            }
        }
        float o[16];
        #pragma unroll
        for (int j = 0; j < 8; j++) {
            float lo, hi; unpack2(acc3[j], lo, hi);
            o[2*j] = elu1(lo); o[2*j+1] = elu1(hi);
        }
        float* op = out + (size_t)v * (FN * 9) + f * 9;
        #pragma unroll
        for (int j = 0; j < 9; j++) op[j] = o[j];
    }
}

extern "C" void kernel_launch(void* const* d_in, const int* in_sizes, int n_in,
                              void* d_out, int out_size)
{
    (void)in_sizes; (void)n_in; (void)out_size;
    const float* coords = (const float*)d_in[0];
    const float* distsq = (const float*)d_in[1];
    const float* feats  = (const float*)d_in[2];
    const int*   nidx   = (const int*)  d_in[3];
    const float* W0 = (const float*)d_in[4];
    const float* b0 = (const float*)d_in[5];
    const float* W1 = (const float*)d_in[6];
    const float* b1 = (const float*)d_in[7];
    const float* W2 = (const float*)d_in[8];
    const float* b2 = (const float*)d_in[9];
    const float* W3 = (const float*)d_in[10];
    const float* b3 = (const float*)d_in[11];

    dim3 grid(V_TOT / 8);   // 100000 % 8 == 0 -> exact
    napca_kernel<<<grid, 128>>>(coords, distsq, feats, nidx,
                                W0, b0, W1, b1, W2, b2, W3, b3,
                                (float*)d_out);
}

// round 7
// speedup vs baseline: 1.1702x; 1.1702x over previous
#include <cuda_runtime.h>

#define V_TOT 100000
#define KN    64
#define FN    16

typedef unsigned long long u64;

// ---- packed f32x2 helpers (Blackwell FFMA2; ptxas never emits from C++) ----
__device__ __forceinline__ u64 pack2s(float a) {           // splat
    u64 r;
    asm("mov.b64 %0, {%1, %1};" : "=l"(r) : "r"(__float_as_uint(a)));
    return r;
}
__device__ __forceinline__ void unpack2(u64 v, float& a, float& b) {
    unsigned lo, hi;
    asm("mov.b64 {%0, %1}, %2;" : "=r"(lo), "=r"(hi) : "l"(v));
    a = __uint_as_float(lo); b = __uint_as_float(hi);
}
__device__ __forceinline__ u64 fma2(u64 a, u64 b, u64 c) {
    u64 d;
    asm("fma.rn.f32x2 %0, %1, %2, %3;" : "=l"(d) : "l"(a), "l"(b), "l"(c));
    return d;
}
__device__ __forceinline__ float elu1(float x) {
    return x > 0.f ? x : (__expf(x) - 1.f);
}

__global__ __launch_bounds__(128, 3)
void napca_kernel(const float* __restrict__ coords,
                  const float* __restrict__ distsq,
                  const float* __restrict__ feats,
                  const int*   __restrict__ nidx,
                  const float* __restrict__ W0, const float* __restrict__ b0,
                  const float* __restrict__ W1, const float* __restrict__ b1,
                  const float* __restrict__ W2, const float* __restrict__ b2,
                  const float* __restrict__ W3, const float* __restrict__ b3,
                  float* __restrict__ out)
{
    __shared__ __align__(16) float sW0[9 * 64];
    __shared__ __align__(16) float sW1[64 * 64];
    __shared__ __align__(16) float sW2[64 * 64];
    __shared__ __align__(16) float sW3[64 * 16];   // W3 [64,9] padded to [64,16]
    __shared__ __align__(16) float sb0[64], sb1[64], sb2[64];
    __shared__ __align__(16) float sb3[16];
    __shared__ __align__(16) float4 sC[8 * KN];    // (cx,cy,cz,exp(-10*d2))
    __shared__ int sIdx[8 * KN];

    const int tid = threadIdx.x;
    const int v0  = blockIdx.x * 8;

    // ---- staging ----
    for (int i = tid; i < 9 * 64;  i += 128) sW0[i] = W0[i];
    for (int i = tid; i < 64 * 64; i += 128) { sW1[i] = W1[i]; sW2[i] = W2[i]; }
    for (int i = tid; i < 64 * 16; i += 128) {
        int c = i & 15;
        sW3[i] = (c < 9) ? W3[(i >> 4) * 9 + c] : 0.f;
    }
    if (tid < 64) { sb0[tid] = b0[tid]; sb1[tid] = b1[tid]; sb2[tid] = b2[tid]; }
    if (tid < 16) sb3[tid] = (tid < 9) ? b3[tid] : 0.f;

    #pragma unroll
    for (int t = 0; t < 4; t++) {
        int i   = tid + t * 128;
        int g   = v0 * KN + i;
        int idx = nidx[g];
        sIdx[i] = idx;
        float e = __expf(-10.f * distsq[g]);
        const float* cp = coords + idx * 3;
        sC[i] = make_float4(cp[0], cp[1], cp[2], e);
    }
    __syncthreads();

    // thread pair (lane^1): p = column half; q selects (vertex, feature-pair)
    const int p  = tid & 1;
    const int q  = tid >> 1;         // 0..63
    const int vl = q >> 3;           // 0..7
    const int fp = q & 7;            // feature pair: f0=2fp, f1=2fp+1
    const int v  = v0 + vl;

    // ---- covariance, k-split across the pair ----
    float s0=0.f, mx0=0.f, my0=0.f, mz0=0.f, pxx0=0.f, pxy0=0.f, pxz0=0.f, pyy0=0.f, pyz0=0.f, pzz0=0.f;
    float s1=0.f, mx1=0.f, my1=0.f, mz1=0.f, pxx1=0.f, pxy1=0.f, pxz1=0.f, pyy1=0.f, pyz1=0.f, pzz1=0.f;
    {
        const float4* cb = sC   + vl * KN + 32 * p;
        const int*    ib = sIdx + vl * KN + 32 * p;
        #pragma unroll 4
        for (int k = 0; k < 32; k++) {
            float4 c  = cb[k];
            float2 wf = __ldg((const float2*)(feats + (size_t)ib[k] * FN + 2 * fp));
            float w0 = wf.x * c.w, w1 = wf.y * c.w;
            s0 += w0; s1 += w1;
            float wx0 = w0*c.x, wy0 = w0*c.y, wz0 = w0*c.z;
            float wx1 = w1*c.x, wy1 = w1*c.y, wz1 = w1*c.z;
            mx0 += wx0; my0 += wy0; mz0 += wz0;
            mx1 += wx1; my1 += wy1; mz1 += wz1;
            pxx0 = fmaf(wx0, c.x, pxx0); pxy0 = fmaf(wx0, c.y, pxy0); pxz0 = fmaf(wx0, c.z, pxz0);
            pyy0 = fmaf(wy0, c.y, pyy0); pyz0 = fmaf(wy0, c.z, pyz0); pzz0 = fmaf(wz0, c.z, pzz0);
            pxx1 = fmaf(wx1, c.x, pxx1); pxy1 = fmaf(wx1, c.y, pxy1); pxz1 = fmaf(wx1, c.z, pxz1);
            pyy1 = fmaf(wy1, c.y, pyy1); pyz1 = fmaf(wy1, c.z, pyz1); pzz1 = fmaf(wz1, c.z, pzz1);
        }
    }
    #define CMB(x) x += __shfl_xor_sync(0xffffffffu, x, 1)
    CMB(s0); CMB(mx0); CMB(my0); CMB(mz0);
    CMB(pxx0); CMB(pxy0); CMB(pxz0); CMB(pyy0); CMB(pyz0); CMB(pzz0);
    CMB(s1); CMB(mx1); CMB(my1); CMB(mz1);
    CMB(pxx1); CMB(pxy1); CMB(pxz1); CMB(pyy1); CMB(pyz1); CMB(pzz1);
    #undef CMB

    float x9a[9], x9b[9];
    {
        float inv = 1.f / (s0 + 1e-4f);
        float ux = mx0*inv, uy = my0*inv, uz = mz0*inv;
        x9a[0] = fmaf(-ux, ux, pxx0*inv);
        x9a[1] = fmaf(-ux, uy, pxy0*inv);
        x9a[2] = fmaf(-ux, uz, pxz0*inv);
        x9a[3] = x9a[1];
        x9a[4] = fmaf(-uy, uy, pyy0*inv);
        x9a[5] = fmaf(-uy, uz, pyz0*inv);
        x9a[6] = x9a[2];
        x9a[7] = x9a[5];
        x9a[8] = fmaf(-uz, uz, pzz0*inv);
    }
    {
        float inv = 1.f / (s1 + 1e-4f);
        float ux = mx1*inv, uy = my1*inv, uz = mz1*inv;
        x9b[0] = fmaf(-ux, ux, pxx1*inv);
        x9b[1] = fmaf(-ux, uy, pxy1*inv);
        x9b[2] = fmaf(-ux, uz, pxz1*inv);
        x9b[3] = x9b[1];
        x9b[4] = fmaf(-uy, uy, pyy1*inv);
        x9b[5] = fmaf(-uy, uz, pyz1*inv);
        x9b[6] = x9b[2];
        x9b[7] = x9b[5];
        x9b[8] = fmaf(-uz, uz, pzz1*inv);
    }

    const int base = 32 * p;          // this thread's column half

    // activations (this thread's 32 columns, both rows)
    float m0[32], m1[32];

    // ---- layer 0: 9 -> 64 (both rows' x9 in-register; weights shared) ----
    {
        u64 acc0[16], acc1[16];
        const ulonglong2* bb = (const ulonglong2*)(sb0 + base);
        #pragma unroll
        for (int jq = 0; jq < 8; jq++) {
            ulonglong2 t = bb[jq];
            acc0[2*jq] = t.x; acc0[2*jq+1] = t.y;
            acc1[2*jq] = t.x; acc1[2*jq+1] = t.y;
        }
        #pragma unroll
        for (int i = 0; i < 9; i++) {
            u64 xa = pack2s(x9a[i]);
            u64 xb = pack2s(x9b[i]);
            const ulonglong2* row = (const ulonglong2*)(sW0 + i * 64 + base);
            #pragma unroll
            for (int jq = 0; jq < 8; jq++) {
                ulonglong2 wv = row[jq];
                acc0[2*jq]   = fma2(xa, wv.x, acc0[2*jq]);
                acc0[2*jq+1] = fma2(xa, wv.y, acc0[2*jq+1]);
                acc1[2*jq]   = fma2(xb, wv.x, acc1[2*jq]);
                acc1[2*jq+1] = fma2(xb, wv.y, acc1[2*jq+1]);
            }
        }
        #pragma unroll
        for (int j = 0; j < 16; j++) {
            float lo, hi;
            unpack2(acc0[j], lo, hi); m0[2*j] = elu1(lo); m0[2*j+1] = elu1(hi);
            unpack2(acc1[j], lo, hi); m1[2*j] = elu1(lo); m1[2*j+1] = elu1(hi);
        }
    }

    // ---- layers 1,2: 64 -> 64 (shfl exchanges partner's activation half) ----
    #pragma unroll 1
    for (int layer = 0; layer < 2; layer++) {
        const float* W = (layer == 0) ? sW1 : sW2;
        const float* B = (layer == 0) ? sb1 : sb2;
        u64 acc0[16], acc1[16];
        const ulonglong2* bb = (const ulonglong2*)(B + base);
        #pragma unroll
        for (int jq = 0; jq < 8; jq++) {
            ulonglong2 t = bb[jq];
            acc0[2*jq] = t.x; acc0[2*jq+1] = t.y;
            acc1[2*jq] = t.x; acc1[2*jq+1] = t.y;
        }
        #pragma unroll
        for (int ii = 0; ii < 32; ii++) {
            float t0 = __shfl_xor_sync(0xffffffffu, m0[ii], 1);
            float t1 = __shfl_xor_sync(0xffffffffu, m1[ii], 1);
            // absolute channel ii owned by p=0, channel 32+ii owned by p=1
            float a0lo = p ? t0 : m0[ii], a0hi = p ? m0[ii] : t0;
            float a1lo = p ? t1 : m1[ii], a1hi = p ? m1[ii] : t1;
            u64 x0lo = pack2s(a0lo), x0hi = pack2s(a0hi);
            u64 x1lo = pack2s(a1lo), x1hi = pack2s(a1hi);
            const ulonglong2* rlo = (const ulonglong2*)(W + ii * 64 + base);
            const ulonglong2* rhi = (const ulonglong2*)(W + (32 + ii) * 64 + base);
            #pragma unroll
            for (int jq = 0; jq < 8; jq++) {
                ulonglong2 wl = rlo[jq];
                ulonglong2 wh = rhi[jq];
                acc0[2*jq]   = fma2(x0lo, wl.x, acc0[2*jq]);
                acc0[2*jq+1] = fma2(x0lo, wl.y, acc0[2*jq+1]);
                acc0[2*jq]   = fma2(x0hi, wh.x, acc0[2*jq]);
                acc0[2*jq+1] = fma2(x0hi, wh.y, acc0[2*jq+1]);
                acc1[2*jq]   = fma2(x1lo, wl.x, acc1[2*jq]);
                acc1[2*jq+1] = fma2(x1lo, wl.y, acc1[2*jq+1]);
                acc1[2*jq]   = fma2(x1hi, wh.x, acc1[2*jq]);
                acc1[2*jq+1] = fma2(x1hi, wh.y, acc1[2*jq+1]);
            }
        }
        #pragma unroll
        for (int j = 0; j < 16; j++) {
            float lo, hi;
            unpack2(acc0[j], lo, hi); m0[2*j] = elu1(lo); m0[2*j+1] = elu1(hi);
            unpack2(acc1[j], lo, hi); m1[2*j] = elu1(lo); m1[2*j+1] = elu1(hi);
        }
    }

    // ---- layer 3: 64 -> 9 (padded 16); this thread: cols [8p, 8p+8) ----
    float o0[8], o1[8];
    {
        const int b3o = 8 * p;
        u64 acc0[4], acc1[4];
        const ulonglong2* bb = (const ulonglong2*)(sb3 + b3o);
        #pragma unroll
        for (int jq = 0; jq < 2; jq++) {
            ulonglong2 t = bb[jq];
            acc0[2*jq] = t.x; acc0[2*jq+1] = t.y;
            acc1[2*jq] = t.x; acc1[2*jq+1] = t.y;
        }
        #pragma unroll
        for (int ii = 0; ii < 32; ii++) {
            float t0 = __shfl_xor_sync(0xffffffffu, m0[ii], 1);
            float t1 = __shfl_xor_sync(0xffffffffu, m1[ii], 1);
            float a0lo = p ? t0 : m0[ii], a0hi = p ? m0[ii] : t0;
            float a1lo = p ? t1 : m1[ii], a1hi = p ? m1[ii] : t1;
            u64 x0lo = pack2s(a0lo), x0hi = pack2s(a0hi);
            u64 x1lo = pack2s(a1lo), x1hi = pack2s(a1hi);
            const ulonglong2* rlo = (const ulonglong2*)(sW3 + ii * 16 + b3o);
            const ulonglong2* rhi = (const ulonglong2*)(sW3 + (32 + ii) * 16 + b3o);
            #pragma unroll
            for (int jq = 0; jq < 2; jq++) {
                ulonglong2 wl = rlo[jq];
                ulonglong2 wh = rhi[jq];
                acc0[2*jq]   = fma2(x0lo, wl.x, acc0[2*jq]);
                acc0[2*jq+1] = fma2(x0lo, wl.y, acc0[2*jq+1]);
                acc0[2*jq]   = fma2(x0hi, wh.x, acc0[2*jq]);
                acc0[2*jq+1] = fma2(x0hi, wh.y, acc0[2*jq+1]);
                acc1[2*jq]   = fma2(x1lo, wl.x, acc1[2*jq]);
                acc1[2*jq+1] = fma2(x1lo, wl.y, acc1[2*jq+1]);
                acc1[2*jq]   = fma2(x1hi, wh.x, acc1[2*jq]);
                acc1[2*jq+1] = fma2(x1hi, wh.y, acc1[2*jq+1]);
            }
        }
        #pragma unroll
        for (int j = 0; j < 4; j++) {
            float lo, hi;
            unpack2(acc0[j], lo, hi); o0[2*j] = elu1(lo); o0[2*j+1] = elu1(hi);
            unpack2(acc1[j], lo, hi); o1[2*j] = elu1(lo); o1[2*j+1] = elu1(hi);
        }
    }

    // ---- store: row0 = (v, 2fp), row1 = (v, 2fp+1); 9 outputs each ----
    float* op0 = out + ((size_t)v * FN + 2 * fp) * 9;
    float* op1 = op0 + 9;
    if (p == 0) {
        #pragma unroll
        for (int j = 0; j < 8; j++) { op0[j] = o0[j]; op1[j] = o1[j]; }
    } else {
        op0[8] = o0[0];   // absolute col 8 is the first of p=1's half
        op1[8] = o1[0];
    }
}

extern "C" void kernel_launch(void* const* d_in, const int* in_sizes, int n_in,
                              void* d_out, int out_size)
{
    (void)in_sizes; (void)n_in; (void)out_size;
    const float* coords = (const float*)d_in[0];
    const float* distsq = (const float*)d_in[1];
    const float* feats  = (const float*)d_in[2];
    const int*   nidx   = (const int*)  d_in[3];
    const float* W0 = (const float*)d_in[4];
    const float* b0 = (const float*)d_in[5];
    const float* W1 = (const float*)d_in[6];
    const float* b1 = (const float*)d_in[7];
    const float* W2 = (const float*)d_in[8];
    const float* b2 = (const float*)d_in[9];
    const float* W3 = (const float*)d_in[10];
    const float* b3 = (const float*)d_in[11];

    dim3 grid(V_TOT / 8);
    napca_kernel<<<grid, 128>>>(coords, distsq, feats, nidx,
                                W0, b0, W1, b1, W2, b2, W3, b3,
                                (float*)d_out);
}